// round 5
// baseline (speedup 1.0000x reference)
#include <cuda_runtime.h>
#include <cuda_bf16.h>

// ContourIntegrationLayer: depthwise 3x3 conv (center tap zeroed) + residual.
// x: [B=32, H=56, W=56, C=256] fp32 NHWC ; kernel: [3,3,256] fp32.
//
// R5: float2-per-thread + packed f32x2 math to halve register footprint
// (taps 32->16 regs) and lift occupancy: 48-reg cap -> 5 blocks/SM ->
// 1280 threads (62.5% occ, 40 warps). Rotating accumulators, one row of
// loads per output row, clamped halo addresses with boundary-zeroed taps.

#define BD 32
#define HD 56
#define WD 56
#define CD 256
#define C2D 128           // CD / 2 float2 lanes
#define H_SEG 14          // 56 / 4 segments
#define W_TILE 2

typedef unsigned long long u64_t;   // packed float2

__device__ __forceinline__ u64_t fma2(u64_t k, u64_t v, u64_t a) {
    u64_t d;
    asm("fma.rn.f32x2 %0, %1, %2, %3;" : "=l"(d) : "l"(k), "l"(v), "l"(a));
    return d;
}
__device__ __forceinline__ u64_t add2(u64_t a, u64_t b) {
    u64_t d;
    asm("add.rn.f32x2 %0, %1, %2;" : "=l"(d) : "l"(a), "l"(b));
    return d;
}
__device__ __forceinline__ u64_t mul2(u64_t a, u64_t b) {
    u64_t d;
    asm("mul.rn.f32x2 %0, %1, %2;" : "=l"(d) : "l"(a), "l"(b));
    return d;
}

__global__ __launch_bounds__(256, 5)
void contour_integration_kernel(const float* __restrict__ x,
                                const float* __restrict__ ker,
                                float* __restrict__ out) {
    const int c2 = threadIdx.x;                       // 0..127
    const int w  = blockIdx.x * W_TILE + threadIdx.y; // 0..55
    const int h0 = blockIdx.y * H_SEG;
    const int b  = blockIdx.z;

    const bool wl = (w > 0);
    const bool wr = (w < WD - 1);
    const u64_t z = 0ull;                             // packed (0.f, 0.f)

    // Per-channel-pair taps; boundary columns zeroed so clamped halo loads
    // contribute nothing. Center (1,1) excluded by construction.
    const u64_t* kp = (const u64_t*)ker;
    const u64_t k00 = wl ? kp[0 * C2D + c2] : z;
    const u64_t k01 =      kp[1 * C2D + c2];
    const u64_t k02 = wr ? kp[2 * C2D + c2] : z;
    const u64_t k10 = wl ? kp[3 * C2D + c2] : z;
    const u64_t k12 = wr ? kp[5 * C2D + c2] : z;
    const u64_t k20 = wl ? kp[6 * C2D + c2] : z;
    const u64_t k21 =      kp[7 * C2D + c2];
    const u64_t k22 = wr ? kp[8 * C2D + c2] : z;

    // Clamped halo offsets: boundary threads re-load center (L1 hit).
    const int offL = wl ? -C2D : 0;
    const int offR = wr ?  C2D : 0;

    const u64_t* xp = (const u64_t*)x;
    u64_t*       op = (u64_t*)out;

    const int rowstride = WD * C2D;                       // 7168 u64 units
    const int base = ((b * HD) * WD + w) * C2D + c2;      // < 2^24, fits int

    u64_t a0, a1;   // a0: partial of out[row]; a1: partial of out[row+1]

    // Input row h0-1 -> top-tap contribution to out[h0].
    if (h0 > 0) {
        const u64_t* p = xp + base + (h0 - 1) * rowstride;
        const u64_t xl = p[offL], xc = p[0], xr = p[offR];
        a1 = fma2(k02, xr, fma2(k00, xl, mul2(k01, xc)));
    } else {
        a1 = z;
    }

    // Input row h0 -> mid taps + residual to out[h0]; top taps to out[h0+1].
    {
        const u64_t* p = xp + base + h0 * rowstride;
        const u64_t xl = p[offL], xc = p[0], xr = p[offR];
        a0 = fma2(k12, xr, fma2(k10, xl, add2(a1, xc)));
        a1 = fma2(k02, xr, fma2(k00, xl, mul2(k01, xc)));
    }

    // Input rows h0+1 .. h0+H_SEG-1: finalize out[hi-1], advance partials.
    #pragma unroll
    for (int i = 1; i < H_SEG; ++i) {
        const int hi = h0 + i;
        const u64_t* p = xp + base + hi * rowstride;
        const u64_t xl = p[offL], xc = p[0], xr = p[offR];

        // bottom taps close out[hi-1]
        const u64_t o = fma2(k22, xr, fma2(k21, xc, fma2(k20, xl, a0)));
        __stcs(op + base + (hi - 1) * rowstride, o);

        a0 = fma2(k12, xr, fma2(k10, xl, add2(a1, xc)));
        a1 = fma2(k02, xr, fma2(k00, xl, mul2(k01, xc)));
    }

    // Input row h0+H_SEG -> bottom-tap contribution to out[h0+H_SEG-1].
    {
        const int hb = h0 + H_SEG;
        if (hb < HD) {
            const u64_t* p = xp + base + hb * rowstride;
            const u64_t xl = p[offL], xc = p[0], xr = p[offR];
            a0 = fma2(k22, xr, fma2(k21, xc, fma2(k20, xl, a0)));
        }
        __stcs(op + base + (hb - 1) * rowstride, a0);
    }
}

extern "C" void kernel_launch(void* const* d_in, const int* in_sizes, int n_in,
                              void* d_out, int out_size) {
    const float* x   = (const float*)d_in[0];   // [32,56,56,256]
    const float* ker = (const float*)d_in[1];   // [3,3,256]
    float*       out = (float*)d_out;

    dim3 block(C2D, W_TILE);                    // 128 x 2 = 256 threads
    dim3 grid(WD / W_TILE, HD / H_SEG, BD);     // 28 x 4 x 32 = 3584 blocks
    contour_integration_kernel<<<grid, block>>>(x, ker, out);
}

// round 7
// speedup vs baseline: 1.2861x; 1.2861x over previous
#include <cuda_runtime.h>
#include <cuda_bf16.h>

// ContourIntegrationLayer: depthwise 3x3 conv (center tap zeroed) + residual.
// x: [B=32, H=56, W=56, C=256] fp32 NHWC ; kernel: [3,3,256] fp32.
//
// R6 (resubmit; prior bench was an infra failure): R2 schedule (float4
// LDG.128 rows, rotating accumulators, clamped halo addresses, boundary-
// zeroed taps) but ALL math as packed fma.rn.f32x2 on the two 64-bit halves
// of each float4 -> FP instruction count halved (36 -> 18 per warp-iter)
// at identical register footprint / occupancy.

#define BD 32
#define HD 56
#define WD 56
#define CD 256
#define C4D 64            // CD / 4 float4 lanes
#define H_SEG 14          // 56 / 4 segments
#define W_TILE 4

typedef unsigned long long u64_t;   // packed float pair

__device__ __forceinline__ u64_t fma2(u64_t k, u64_t v, u64_t a) {
    u64_t d;
    asm("fma.rn.f32x2 %0, %1, %2, %3;" : "=l"(d) : "l"(k), "l"(v), "l"(a));
    return d;
}
__device__ __forceinline__ u64_t add2(u64_t a, u64_t b) {
    u64_t d;
    asm("add.rn.f32x2 %0, %1, %2;" : "=l"(d) : "l"(a), "l"(b));
    return d;
}
__device__ __forceinline__ u64_t mul2(u64_t a, u64_t b) {
    u64_t d;
    asm("mul.rn.f32x2 %0, %1, %2;" : "=l"(d) : "l"(a), "l"(b));
    return d;
}
__device__ __forceinline__ u64_t lo64(float4 v) {
    u64_t r; asm("mov.b64 %0, {%1, %2};" : "=l"(r) : "f"(v.x), "f"(v.y)); return r;
}
__device__ __forceinline__ u64_t hi64(float4 v) {
    u64_t r; asm("mov.b64 %0, {%1, %2};" : "=l"(r) : "f"(v.z), "f"(v.w)); return r;
}
__device__ __forceinline__ float4 pack4(u64_t a, u64_t b) {
    float4 v;
    asm("mov.b64 {%0, %1}, %2;" : "=f"(v.x), "=f"(v.y) : "l"(a));
    asm("mov.b64 {%0, %1}, %2;" : "=f"(v.z), "=f"(v.w) : "l"(b));
    return v;
}

__global__ __launch_bounds__(256, 4)
void contour_integration_kernel(const float* __restrict__ x,
                                const float* __restrict__ ker,
                                float* __restrict__ out) {
    const int c4 = threadIdx.x;                       // 0..63
    const int w  = blockIdx.x * W_TILE + threadIdx.y; // 0..55
    const int h0 = blockIdx.y * H_SEG;
    const int b  = blockIdx.z;

    const bool wl = (w > 0);
    const bool wr = (w < WD - 1);
    const u64_t z = 0ull;
    const float4 zf = make_float4(0.f, 0.f, 0.f, 0.f);

    // Per-channel taps as packed pairs; boundary columns zeroed so clamped
    // halo loads contribute nothing. Center (1,1) excluded by construction.
    const float4* kp = (const float4*)ker;
    const float4 t00 = wl ? kp[0 * C4D + c4] : zf;
    const float4 t01 =      kp[1 * C4D + c4];
    const float4 t02 = wr ? kp[2 * C4D + c4] : zf;
    const float4 t10 = wl ? kp[3 * C4D + c4] : zf;
    const float4 t12 = wr ? kp[5 * C4D + c4] : zf;
    const float4 t20 = wl ? kp[6 * C4D + c4] : zf;
    const float4 t21 =      kp[7 * C4D + c4];
    const float4 t22 = wr ? kp[8 * C4D + c4] : zf;
    const u64_t k00a = lo64(t00), k00b = hi64(t00);
    const u64_t k01a = lo64(t01), k01b = hi64(t01);
    const u64_t k02a = lo64(t02), k02b = hi64(t02);
    const u64_t k10a = lo64(t10), k10b = hi64(t10);
    const u64_t k12a = lo64(t12), k12b = hi64(t12);
    const u64_t k20a = lo64(t20), k20b = hi64(t20);
    const u64_t k21a = lo64(t21), k21b = hi64(t21);
    const u64_t k22a = lo64(t22), k22b = hi64(t22);

    // Clamped halo offsets: boundary threads re-load center (L1 hit).
    const int offL = wl ? -C4D : 0;
    const int offR = wr ?  C4D : 0;

    const float4* xp = (const float4*)x;
    float4*       op = (float4*)out;

    const int rowstride = WD * C4D;                  // 3584 float4 units
    const int base = ((b * HD) * WD + w) * C4D + c4; // < 2^23, fits int

    u64_t a0a, a0b, a1a, a1b;   // partials of out[row], out[row+1]

    // Input row h0-1 -> top-tap contribution to out[h0].
    if (h0 > 0) {
        const float4* p = xp + base + (h0 - 1) * rowstride;
        const float4 xl = p[offL], xc = p[0], xr = p[offR];
        a1a = fma2(k02a, lo64(xr), fma2(k00a, lo64(xl), mul2(k01a, lo64(xc))));
        a1b = fma2(k02b, hi64(xr), fma2(k00b, hi64(xl), mul2(k01b, hi64(xc))));
    } else {
        a1a = z; a1b = z;
    }

    // Input row h0 -> mid taps + residual to out[h0]; top taps to out[h0+1].
    {
        const float4* p = xp + base + h0 * rowstride;
        const float4 xl = p[offL], xc = p[0], xr = p[offR];
        const u64_t xla = lo64(xl), xlb = hi64(xl);
        const u64_t xca = lo64(xc), xcb = hi64(xc);
        const u64_t xra = lo64(xr), xrb = hi64(xr);
        a0a = fma2(k12a, xra, fma2(k10a, xla, add2(a1a, xca)));
        a0b = fma2(k12b, xrb, fma2(k10b, xlb, add2(a1b, xcb)));
        a1a = fma2(k02a, xra, fma2(k00a, xla, mul2(k01a, xca)));
        a1b = fma2(k02b, xrb, fma2(k00b, xlb, mul2(k01b, xcb)));
    }

    // Input rows h0+1 .. h0+H_SEG-1: finalize out[hi-1], advance partials.
    #pragma unroll
    for (int i = 1; i < H_SEG; ++i) {
        const int hi = h0 + i;
        const float4* p = xp + base + hi * rowstride;
        const float4 xl = p[offL], xc = p[0], xr = p[offR];
        const u64_t xla = lo64(xl), xlb = hi64(xl);
        const u64_t xca = lo64(xc), xcb = hi64(xc);
        const u64_t xra = lo64(xr), xrb = hi64(xr);

        // bottom taps close out[hi-1]
        const u64_t oa = fma2(k22a, xra, fma2(k21a, xca, fma2(k20a, xla, a0a)));
        const u64_t ob = fma2(k22b, xrb, fma2(k21b, xcb, fma2(k20b, xlb, a0b)));
        __stcs(op + base + (hi - 1) * rowstride, pack4(oa, ob));

        a0a = fma2(k12a, xra, fma2(k10a, xla, add2(a1a, xca)));
        a0b = fma2(k12b, xrb, fma2(k10b, xlb, add2(a1b, xcb)));
        a1a = fma2(k02a, xra, fma2(k00a, xla, mul2(k01a, xca)));
        a1b = fma2(k02b, xrb, fma2(k00b, xlb, mul2(k01b, xcb)));
    }

    // Input row h0+H_SEG -> bottom-tap contribution to out[h0+H_SEG-1].
    {
        const int hb = h0 + H_SEG;
        if (hb < HD) {
            const float4* p = xp + base + hb * rowstride;
            const float4 xl = p[offL], xc = p[0], xr = p[offR];
            a0a = fma2(k22a, lo64(xr), fma2(k21a, lo64(xc), fma2(k20a, lo64(xl), a0a)));
            a0b = fma2(k22b, hi64(xr), fma2(k21b, hi64(xc), fma2(k20b, hi64(xl), a0b)));
        }
        __stcs(op + base + (hb - 1) * rowstride, pack4(a0a, a0b));
    }
}

extern "C" void kernel_launch(void* const* d_in, const int* in_sizes, int n_in,
                              void* d_out, int out_size) {
    const float* x   = (const float*)d_in[0];   // [32,56,56,256]
    const float* ker = (const float*)d_in[1];   // [3,3,256]
    float*       out = (float*)d_out;

    dim3 block(C4D, W_TILE);                    // 64 x 4 = 256 threads
    dim3 grid(WD / W_TILE, HD / H_SEG, BD);     // 14 x 4 x 32 = 1792 blocks
    contour_integration_kernel<<<grid, block>>>(x, ker, out);
}

// round 10
// speedup vs baseline: 1.5455x; 1.2017x over previous
#include <cuda_runtime.h>
#include <cuda_bf16.h>

// ContourIntegrationLayer: depthwise 3x3 conv (center tap zeroed) + residual.
// x: [B=32, H=56, W=56, C=256] fp32 NHWC ; kernel: [3,3,256] fp32.
//
// R8 (second identical resubmit; two prior benches were broker/container
// failures with no kernel signal): cp.async (LDGSTS) 5-stage smem ring + R2
// scalar rotating-accumulator compute. Latency hiding moves off the register
// file: 3 rows of copies in flight per block (18KB) at zero register cost.
// Compute reads staged rows via LDS.128 (29cyc, hidden by FMA chain).
// Clamped w-halo at copy time, boundary-zeroed taps. Same grid/occupancy as
// R2 (1792 blocks, 64 regs target).

#define BD 32
#define HD 56
#define WD 56
#define CD 256
#define C4D 64             // CD/4 float4 lanes
#define H_SEG 14           // 4 segments
#define W_TILE 4
#define NS 5               // smem ring stages
#define ROWSTRIDE (WD * C4D)   // 3584 float4 per image row
#define SLICE_F4 (6 * C4D)     // 6 w-slices per stage = 384 float4 = 6KB

__device__ __forceinline__ void cp16(float4* dst_smem, const float4* src) {
    unsigned d = (unsigned)__cvta_generic_to_shared(dst_smem);
    asm volatile("cp.async.cg.shared.global [%0], [%1], 16;" :: "r"(d), "l"(src));
}
#define CP_COMMIT() asm volatile("cp.async.commit_group;")
#define CP_WAIT2()  asm volatile("cp.async.wait_group 2;")

__device__ __forceinline__ void fma4(float4& a, const float4& k, const float4& v) {
    a.x = fmaf(k.x, v.x, a.x);
    a.y = fmaf(k.y, v.y, a.y);
    a.z = fmaf(k.z, v.z, a.z);
    a.w = fmaf(k.w, v.w, a.w);
}
__device__ __forceinline__ void add4(float4& a, const float4& v) {
    a.x += v.x; a.y += v.y; a.z += v.z; a.w += v.w;
}

__global__ __launch_bounds__(256, 4)
void contour_integration_kernel(const float* __restrict__ x,
                                const float* __restrict__ ker,
                                float* __restrict__ out) {
    __shared__ __align__(16) float4 stg[NS][SLICE_F4];

    const int c4    = threadIdx.x;                 // 0..63
    const int wslot = threadIdx.y;                 // 0..3
    const int tid   = c4 + wslot * C4D;            // 0..255
    const int w0    = blockIdx.x * W_TILE;
    const int w     = w0 + wslot;
    const int h0    = blockIdx.y * H_SEG;
    const int b     = blockIdx.z;

    // ---- copy-role precompute: thread handles chunk tid (+ tid+256 if tid<128)
    const int  s1  = tid >> 6, cc1 = tid & 63;
    const int  ws1 = min(max(w0 - 1 + s1, 0), WD - 1);      // clamped w source
    const float4* src1 = (const float4*)x + ((b * HD) * WD + ws1) * C4D + cc1;
    const int  q2  = tid + 256;
    const int  s2  = q2 >> 6, cc2 = q2 & 63;
    const int  ws2 = min(max(w0 - 1 + s2, 0), WD - 1);
    const float4* src2 = (const float4*)x + ((b * HD) * WD + ws2) * C4D + cc2;
    const bool do2 = (tid < 128);

    // ---- compute-role precompute
    const bool wl = (w > 0);
    const bool wr = (w < WD - 1);
    const float4 zf = make_float4(0.f, 0.f, 0.f, 0.f);
    const float4* kp = (const float4*)ker;
    const float4 k00 = wl ? kp[0 * C4D + c4] : zf;
    const float4 k01 =      kp[1 * C4D + c4];
    const float4 k02 = wr ? kp[2 * C4D + c4] : zf;
    const float4 k10 = wl ? kp[3 * C4D + c4] : zf;
    const float4 k12 = wr ? kp[5 * C4D + c4] : zf;
    const float4 k20 = wl ? kp[6 * C4D + c4] : zf;
    const float4 k21 =      kp[7 * C4D + c4];
    const float4 k22 = wr ? kp[8 * C4D + c4] : zf;

    const int out_base = ((b * HD) * WD + w) * C4D + c4;
    float4* op = (float4*)out;

    // Prologue: issue copies for i = 0,1,2 (rows h0-1, h0, h0+1).
    #pragma unroll
    for (int i = 0; i < 3; ++i) {
        const int r = h0 - 1 + i;
        if (r >= 0 && r < HD) {
            cp16(&stg[i][tid], src1 + r * ROWSTRIDE);
            if (do2) cp16(&stg[i][q2], src2 + r * ROWSTRIDE);
        }
        CP_COMMIT();
    }

    float4 a0 = zf, a1 = zf;   // partials of out[r], out[r+1] (rotation)

    // Consume input rows r = h0-1+i for i = 0..H_SEG+1 (16 rows).
    #pragma unroll
    for (int i = 0; i <= H_SEG + 1; ++i) {
        // Issue copy for row i+3 into stage (i+3)%NS (WAR distance 4 < 5).
        if (i + 3 <= H_SEG + 1) {
            const int rn = h0 + 2 + i;             // (h0-1) + (i+3)
            if (rn < HD) {
                float4* dst = stg[(i + 3) % NS];
                cp16(&dst[tid], src1 + rn * ROWSTRIDE);
                if (do2) cp16(&dst[q2], src2 + rn * ROWSTRIDE);
            }
        }
        CP_COMMIT();
        CP_WAIT2();                                 // row i (and i+1) landed
        __syncthreads();

        const int r = h0 - 1 + i;
        float4 xl, xc, xr;
        if (r >= 0 && r < HD) {
            const float4* sp = &stg[i % NS][(wslot + 1) * C4D + c4];
            xl = sp[-C4D]; xc = sp[0]; xr = sp[C4D];
        } else {
            xl = zf; xc = zf; xr = zf;              // virtual zero row
        }

        // bottom taps of row r close out[r-1]
        if (i >= 2) {
            float4 o = a0;
            fma4(o, k20, xl); fma4(o, k21, xc); fma4(o, k22, xr);
            __stcs(op + out_base + (r - 1) * ROWSTRIDE, o);
        }

        // advance partials: mid taps + residual -> out[r]; top taps -> out[r+1]
        float4 An = a1;
        add4(An, xc);
        fma4(An, k10, xl); fma4(An, k12, xr);
        float4 Bn = zf;
        fma4(Bn, k00, xl); fma4(Bn, k01, xc); fma4(Bn, k02, xr);
        a0 = An; a1 = Bn;
    }
}

extern "C" void kernel_launch(void* const* d_in, const int* in_sizes, int n_in,
                              void* d_out, int out_size) {
    const float* x   = (const float*)d_in[0];   // [32,56,56,256]
    const float* ker = (const float*)d_in[1];   // [3,3,256]
    float*       outp = (float*)d_out;

    dim3 block(C4D, W_TILE);                    // 64 x 4 = 256 threads
    dim3 grid(WD / W_TILE, HD / H_SEG, BD);     // 14 x 4 x 32 = 1792 blocks
    contour_integration_kernel<<<grid, block>>>(x, ker, outp);
}